// round 7
// baseline (speedup 1.0000x reference)
#include <cuda_runtime.h>
#include <math.h>

#define NN 50000
#define NE 800000
#define XUF 37
#define XUP 40
#define FULLF 28
#define RNN 20
#define RNN_E 8
#define LAT 32

// ---------------- scratch (device globals; no allocations) ----------------
__device__ float g_xu[NN * XUP];
__device__ float g_full[NN * FULLF];
__device__ float g_msum[NN * LAT];
__device__ float g_esum[NN * LAT];
__device__ int   g_cnt[NN];

__device__ __forceinline__ float sigm(float v) { return 1.f / (1.f + expf(-v)); }

__device__ __forceinline__ void fma2(unsigned long long& d,
                                     unsigned long long a, unsigned long long b) {
    asm("fma.rn.f32x2 %0, %1, %2, %0;" : "+l"(d) : "l"(a), "l"(b));
}
__device__ __forceinline__ float2 upk(unsigned long long v) {
    unsigned int lo, hi;
    asm("mov.b64 {%0, %1}, %2;" : "=r"(lo), "=r"(hi) : "l"(v));
    float2 r; r.x = __uint_as_float(lo); r.y = __uint_as_float(hi);
    return r;
}

// ---------------- K1: build xu, node-history LSTM, zero accumulators ------
__global__ void __launch_bounds__(256) k1_node(
    const float* __restrict__ x, const float* __restrict__ u,
    const float* __restrict__ hh, const float* __restrict__ hc,
    const float* __restrict__ Wih, const float* __restrict__ Whh,
    const float* __restrict__ bih, const float* __restrict__ bhh,
    float* __restrict__ outh, float* __restrict__ outc)
{
    __shared__ float sW[80 * 37];
    __shared__ float sU[80 * 20];
    __shared__ float sb[80];
    for (int i = threadIdx.x; i < 80 * 37; i += 256) sW[i] = Wih[i];
    for (int i = threadIdx.x; i < 80 * 20; i += 256) sU[i] = Whh[i];
    for (int i = threadIdx.x; i < 80; i += 256) sb[i] = bih[i] + bhh[i];
    __syncthreads();

    int n = blockIdx.x * 256 + threadIdx.x;
    if (n >= NN) return;

    float xu[37];
#pragma unroll
    for (int k = 0; k < 5; k++)  xu[k] = x[n * 5 + k];
#pragma unroll
    for (int k = 0; k < 32; k++) xu[5 + k] = u[n * 32 + k];
#pragma unroll
    for (int k = 0; k < 37; k++) g_xu[n * XUP + k] = xu[k];
    g_xu[n * XUP + 37] = 0.f; g_xu[n * XUP + 38] = 0.f; g_xu[n * XUP + 39] = 0.f;

    float h[20];
#pragma unroll
    for (int j = 0; j < 20; j++) h[j] = hh[n * 20 + j];

#pragma unroll
    for (int k = 0; k < 32; k++) { g_msum[n * 32 + k] = 0.f; g_esum[n * 32 + k] = 0.f; }
    g_cnt[n] = 0;

    for (int q = 0; q < 20; q++) {
        float gi = sb[q], gf = sb[20 + q], gg = sb[40 + q], go = sb[60 + q];
        const float* wi = &sW[q * 37];
        const float* wf = &sW[(20 + q) * 37];
        const float* wg = &sW[(40 + q) * 37];
        const float* wo = &sW[(60 + q) * 37];
#pragma unroll
        for (int k = 0; k < 37; k++) {
            float v = xu[k];
            gi += v * wi[k]; gf += v * wf[k]; gg += v * wg[k]; go += v * wo[k];
        }
        const float* ui = &sU[q * 20];
        const float* uf = &sU[(20 + q) * 20];
        const float* ug = &sU[(40 + q) * 20];
        const float* uo = &sU[(60 + q) * 20];
#pragma unroll
        for (int j = 0; j < 20; j++) {
            float v = h[j];
            gi += v * ui[j]; gf += v * uf[j]; gg += v * ug[j]; go += v * uo[j];
        }
        float c0 = hc[n * 20 + q];
        float cn = sigm(gf) * c0 + sigm(gi) * tanhf(gg);
        float hn = sigm(go) * tanhf(cn);
        outh[n * 20 + q] = hn;
        outc[n * 20 + q] = cn;
        g_full[n * 28 + q] = hn;
    }
}

// ---------------- edge GEMM kernel (packed f32x2) --------------------------
// Block = 128 edges. Inputs k-major in smem; weights/biases pre-duplicated
// for packed math. Thread tile: 8 edges (as 4 packed pairs) x 8 hidden.
template <int IN, int F, int FP, int NV4>
__global__ void __launch_bounds__(128) edge_gemm(
    const int* __restrict__ ei, const float* __restrict__ ea,
    const float* __restrict__ W1, const float* __restrict__ b1,
    const float* __restrict__ W2, const float* __restrict__ b2,
    const float* __restrict__ feat, float* __restrict__ accum, int doCnt)
{
    extern __shared__ float smem[];
    const int HROWS = (IN > 64) ? IN : 64;
    float* sIn  = smem;                   // [HROWS][128]; aliased as sH[64][128]
    float* sW1d = sIn + HROWS * 128;      // [IN][128] w dup'd: pos 2q,2q+1 = W1[k][q]
    float* sW2d = sW1d + IN * 128;        // [64][64]  w dup'd
    __shared__ __align__(16) float sb1d[128];
    __shared__ __align__(16) float sb2d[64];
    __shared__ int sCol[128];

    const int tid = threadIdx.x;

    // --- stage weights duplicated for packed math ---
    {
        const float4* w1s = (const float4*)W1;
        for (int i = tid; i < IN * 16; i += 128) {
            float4 v = w1s[i];
            int k = i >> 4, qg = i & 15;
            *(float4*)&sW1d[k * 128 + qg * 8]     = make_float4(v.x, v.x, v.y, v.y);
            *(float4*)&sW1d[k * 128 + qg * 8 + 4] = make_float4(v.z, v.z, v.w, v.w);
        }
        const float4* w2s = (const float4*)W2;
        for (int i = tid; i < 64 * 8; i += 128) {
            float4 v = w2s[i];
            int k = i >> 3, qg = i & 7;
            *(float4*)&sW2d[k * 64 + qg * 8]     = make_float4(v.x, v.x, v.y, v.y);
            *(float4*)&sW2d[k * 64 + qg * 8 + 4] = make_float4(v.z, v.z, v.w, v.w);
        }
        if (tid < 64) { float b = b1[tid]; sb1d[2 * tid] = b; sb1d[2 * tid + 1] = b; }
        if (tid < 32) { float b = b2[tid]; sb2d[2 * tid] = b; sb2d[2 * tid + 1] = b; }
    }

    // --- gather: one thread per edge ---
    {
        int e = blockIdx.x * 128 + tid;
        int r = ei[e];
        int c = ei[NE + e];
        sCol[tid] = c;
        if (doCnt) atomicAdd(&g_cnt[c], 1);

        const float4* ps = (const float4*)(feat + (long)r * FP);
        const float4* pd = (const float4*)(feat + (long)c * FP);
#pragma unroll
        for (int j = 0; j < NV4; j++) {
            float4 v = __ldg(ps + j);
            int k = 4 * j;
            if (k + 0 < F) sIn[(k + 0) * 128 + tid] = v.x;
            if (k + 1 < F) sIn[(k + 1) * 128 + tid] = v.y;
            if (k + 2 < F) sIn[(k + 2) * 128 + tid] = v.z;
            if (k + 3 < F) sIn[(k + 3) * 128 + tid] = v.w;
        }
#pragma unroll
        for (int j = 0; j < NV4; j++) {
            float4 v = __ldg(pd + j);
            int k = 4 * j;
            if (k + 0 < F) sIn[(F + k + 0) * 128 + tid] = v.x;
            if (k + 1 < F) sIn[(F + k + 1) * 128 + tid] = v.y;
            if (k + 2 < F) sIn[(F + k + 2) * 128 + tid] = v.z;
            if (k + 3 < F) sIn[(F + k + 3) * 128 + tid] = v.w;
        }
        float4 e4 = __ldg((const float4*)(ea + (long)e * 4));
        sIn[(2 * F + 0) * 128 + tid] = e4.x;
        sIn[(2 * F + 1) * 128 + tid] = e4.y;
        sIn[(2 * F + 2) * 128 + tid] = e4.z;
        sIn[(2 * F + 3) * 128 + tid] = e4.w;
    }
    __syncthreads();

    const int er = tid & 15;           // edge group
    const int hr = tid >> 4;           // hidden group (8 hidden) / out group (4 out)
    const int eb0 = 4 * er;            // edges eb0..eb0+3
    const int eb1 = 64 + 4 * er;       // edges eb1..eb1+3

    // --- GEMM1: 128x64xIN, packed f32x2, tile 4 edge-pairs x 8 hidden ---
    unsigned long long acc[4][8];
    {
#pragma unroll
        for (int j = 0; j < 4; j++) {
            ulonglong2 bq = *(const ulonglong2*)&sb1d[hr * 16 + 4 * j];
#pragma unroll
            for (int p = 0; p < 4; p++) { acc[p][2 * j] = bq.x; acc[p][2 * j + 1] = bq.y; }
        }
    }

#pragma unroll 2
    for (int k = 0; k < IN; k++) {
        const float* rowA = &sIn[k * 128];
        ulonglong2 a01 = *(const ulonglong2*)&rowA[eb0];
        ulonglong2 a23 = *(const ulonglong2*)&rowA[eb1];
        unsigned long long av[4] = {a01.x, a01.y, a23.x, a23.y};
        const float* rowW = &sW1d[k * 128 + hr * 16];
        ulonglong2 wA = *(const ulonglong2*)&rowW[0];
        ulonglong2 wB = *(const ulonglong2*)&rowW[4];
        ulonglong2 wC = *(const ulonglong2*)&rowW[8];
        ulonglong2 wD = *(const ulonglong2*)&rowW[12];
        unsigned long long wv[8] = {wA.x, wA.y, wB.x, wB.y, wC.x, wC.y, wD.x, wD.y};
#pragma unroll
        for (int p = 0; p < 4; p++)
#pragma unroll
            for (int q = 0; q < 8; q++) fma2(acc[p][q], av[p], wv[q]);
    }
    __syncthreads();

    // --- ReLU + store hidden (aliases sIn) ---
    float* sH = sIn;  // [64][128]
#pragma unroll
    for (int q = 0; q < 8; q++) {
        int j = hr * 8 + q;
        float2 r0 = upk(acc[0][q]);
        float2 r1 = upk(acc[1][q]);
        float2 r2 = upk(acc[2][q]);
        float2 r3 = upk(acc[3][q]);
        *(float4*)&sH[j * 128 + eb0] = make_float4(
            fmaxf(r0.x, 0.f), fmaxf(r0.y, 0.f), fmaxf(r1.x, 0.f), fmaxf(r1.y, 0.f));
        *(float4*)&sH[j * 128 + eb1] = make_float4(
            fmaxf(r2.x, 0.f), fmaxf(r2.y, 0.f), fmaxf(r3.x, 0.f), fmaxf(r3.y, 0.f));
    }
    __syncthreads();

    // --- GEMM2: 128x32x64, packed f32x2, tile 4 edge-pairs x 4 out ---
    unsigned long long acc2[4][4];
    {
        ulonglong2 cA = *(const ulonglong2*)&sb2d[hr * 8];
        ulonglong2 cB = *(const ulonglong2*)&sb2d[hr * 8 + 4];
#pragma unroll
        for (int p = 0; p < 4; p++) {
            acc2[p][0] = cA.x; acc2[p][1] = cA.y; acc2[p][2] = cB.x; acc2[p][3] = cB.y;
        }
    }

#pragma unroll 4
    for (int k = 0; k < 64; k++) {
        const float* rowA = &sH[k * 128];
        ulonglong2 a01 = *(const ulonglong2*)&rowA[eb0];
        ulonglong2 a23 = *(const ulonglong2*)&rowA[eb1];
        unsigned long long av[4] = {a01.x, a01.y, a23.x, a23.y};
        const float* rowW = &sW2d[k * 64 + hr * 8];
        ulonglong2 wA = *(const ulonglong2*)&rowW[0];
        ulonglong2 wB = *(const ulonglong2*)&rowW[4];
        unsigned long long wv[4] = {wA.x, wA.y, wB.x, wB.y};
#pragma unroll
        for (int p = 0; p < 4; p++)
#pragma unroll
            for (int q = 0; q < 4; q++) fma2(acc2[p][q], av[p], wv[q]);
    }

    // --- scatter-add: unpack pairs, red.v4 per edge ---
    int ebase[4] = {eb0, eb0 + 2, eb1, eb1 + 2};
#pragma unroll
    for (int p = 0; p < 4; p++) {
        float2 r0 = upk(acc2[p][0]);
        float2 r1 = upk(acc2[p][1]);
        float2 r2 = upk(acc2[p][2]);
        float2 r3 = upk(acc2[p][3]);
        int c0 = sCol[ebase[p]];
        int c1 = sCol[ebase[p] + 1];
        float* d0 = accum + (long)c0 * 32 + hr * 4;
        float* d1 = accum + (long)c1 * 32 + hr * 4;
        asm volatile("red.global.add.v4.f32 [%0], {%1, %2, %3, %4};"
                     :: "l"(d0), "f"(r0.x), "f"(r1.x), "f"(r2.x), "f"(r3.x) : "memory");
        asm volatile("red.global.add.v4.f32 [%0], {%1, %2, %3, %4};"
                     :: "l"(d1), "f"(r0.y), "f"(r1.y), "f"(r2.y), "f"(r3.y) : "memory");
    }
}

// ---------------- K3: segment mean + edge-history LSTM --------------------
__global__ void __launch_bounds__(256) k3_edge_lstm(
    const float* __restrict__ hh, const float* __restrict__ hc,
    const float* __restrict__ Wih, const float* __restrict__ Whh,
    const float* __restrict__ bih, const float* __restrict__ bhh,
    float* __restrict__ outh, float* __restrict__ outc)
{
    __shared__ float sW[32 * 32];
    __shared__ float sU[32 * 8];
    __shared__ float sb[32];
    for (int i = threadIdx.x; i < 32 * 32; i += 256) sW[i] = Wih[i];
    for (int i = threadIdx.x; i < 32 * 8; i += 256)  sU[i] = Whh[i];
    for (int i = threadIdx.x; i < 32; i += 256) sb[i] = bih[i] + bhh[i];
    __syncthreads();

    int n = blockIdx.x * 256 + threadIdx.x;
    if (n >= NN) return;

    float inv = 1.f / fmaxf((float)g_cnt[n], 1.f);
    float a[32];
#pragma unroll
    for (int k = 0; k < 32; k++) a[k] = g_msum[n * 32 + k] * inv;
    float h[8];
#pragma unroll
    for (int j = 0; j < 8; j++) h[j] = hh[n * 8 + j];

    for (int q = 0; q < 8; q++) {
        float gi = sb[q], gf = sb[8 + q], gg = sb[16 + q], go = sb[24 + q];
#pragma unroll
        for (int k = 0; k < 32; k++) {
            float v = a[k];
            gi += v * sW[q * 32 + k];
            gf += v * sW[(8 + q) * 32 + k];
            gg += v * sW[(16 + q) * 32 + k];
            go += v * sW[(24 + q) * 32 + k];
        }
#pragma unroll
        for (int j = 0; j < 8; j++) {
            float v = h[j];
            gi += v * sU[q * 8 + j];
            gf += v * sU[(8 + q) * 8 + j];
            gg += v * sU[(16 + q) * 8 + j];
            go += v * sU[(24 + q) * 8 + j];
        }
        float c0 = hc[n * 8 + q];
        float cn = sigm(gf) * c0 + sigm(gi) * tanhf(gg);
        float hn = sigm(go) * tanhf(cn);
        outh[n * 8 + q] = hn;
        outc[n * 8 + q] = cn;
        g_full[n * 28 + 20 + q] = hn;
    }
}

// ---------------- K5: segment mean + output node MLP ----------------------
__global__ void __launch_bounds__(256) k5_out(
    const float* __restrict__ Wn1, const float* __restrict__ bn1,
    const float* __restrict__ Wn2, const float* __restrict__ bn2,
    float* __restrict__ out)
{
    __shared__ float sW1[60 * 64];
    __shared__ float sW2[64 * 4];
    __shared__ float sb1[64];
    __shared__ float sb2[4];
    for (int i = threadIdx.x; i < 60 * 64; i += 256) sW1[i] = Wn1[i];
    for (int i = threadIdx.x; i < 64 * 4; i += 256)  sW2[i] = Wn2[i];
    if (threadIdx.x < 64) sb1[threadIdx.x] = bn1[threadIdx.x];
    if (threadIdx.x < 4)  sb2[threadIdx.x] = bn2[threadIdx.x];
    __syncthreads();

    int n = blockIdx.x * 256 + threadIdx.x;
    if (n >= NN) return;

    float in[60];
#pragma unroll
    for (int k = 0; k < 28; k++) in[k] = g_full[n * 28 + k];
    float inv = 1.f / fmaxf((float)g_cnt[n], 1.f);
#pragma unroll
    for (int k = 0; k < 32; k++) in[28 + k] = g_esum[n * 32 + k] * inv;

    float o0 = sb2[0], o1 = sb2[1], o2 = sb2[2], o3 = sb2[3];
    for (int jb = 0; jb < 64; jb += 8) {
        float h[8];
#pragma unroll
        for (int q = 0; q < 8; q++) h[q] = sb1[jb + q];
#pragma unroll
        for (int k = 0; k < 60; k++) {
            float v = in[k];
            float4 wa = *(const float4*)&sW1[k * 64 + jb];
            float4 wb = *(const float4*)&sW1[k * 64 + jb + 4];
            h[0] += v * wa.x; h[1] += v * wa.y; h[2] += v * wa.z; h[3] += v * wa.w;
            h[4] += v * wb.x; h[5] += v * wb.y; h[6] += v * wb.z; h[7] += v * wb.w;
        }
#pragma unroll
        for (int q = 0; q < 8; q++) {
            float hv = fmaxf(h[q], 0.f);
            float4 w4 = *(const float4*)&sW2[(jb + q) * 4];
            o0 += hv * w4.x; o1 += hv * w4.y; o2 += hv * w4.z; o3 += hv * w4.w;
        }
    }
    float4 r; r.x = o0; r.y = o1; r.z = o2; r.w = o3;
    *(float4*)(out + (long)n * 4) = r;
}

// ---------------- launch ---------------------------------------------------
extern "C" void kernel_launch(void* const* d_in, const int* in_sizes, int n_in,
                              void* d_out, int out_size)
{
    const float* x     = (const float*)d_in[0];
    const float* u     = (const float*)d_in[1];
    const int*   ei    = (const int*)  d_in[2];
    const float* ea    = (const float*)d_in[3];
    const float* hnh   = (const float*)d_in[4];
    const float* hnc   = (const float*)d_in[5];
    const float* heh   = (const float*)d_in[6];
    const float* hec   = (const float*)d_in[7];
    const float* Wih_n = (const float*)d_in[8];
    const float* Whh_n = (const float*)d_in[9];
    const float* bih_n = (const float*)d_in[10];
    const float* bhh_n = (const float*)d_in[11];
    const float* Wih_e = (const float*)d_in[12];
    const float* Whh_e = (const float*)d_in[13];
    const float* bih_e = (const float*)d_in[14];
    const float* bhh_e = (const float*)d_in[15];
    const float* We1 = (const float*)d_in[16];
    const float* be1 = (const float*)d_in[17];
    const float* We2 = (const float*)d_in[18];
    const float* be2 = (const float*)d_in[19];
    const float* Wo1 = (const float*)d_in[20];
    const float* bo1 = (const float*)d_in[21];
    const float* Wo2 = (const float*)d_in[22];
    const float* bo2 = (const float*)d_in[23];
    const float* Wn1 = (const float*)d_in[24];
    const float* bn1 = (const float*)d_in[25];
    const float* Wn2 = (const float*)d_in[26];
    const float* bn2 = (const float*)d_in[27];

    float* out    = (float*)d_out;
    float* out_y  = out;
    float* out_nh = out_y + (long)NN * 4;
    float* out_nc = out_nh + (long)NN * RNN;
    float* out_eh = out_nc + (long)NN * RNN;
    float* out_ec = out_eh + (long)NN * RNN_E;

    void *p_xu, *p_full, *p_msum, *p_esum;
    cudaGetSymbolAddress(&p_xu,   g_xu);
    cudaGetSymbolAddress(&p_full, g_full);
    cudaGetSymbolAddress(&p_msum, g_msum);
    cudaGetSymbolAddress(&p_esum, g_esum);

    const int smem1 = (78 * 128 + 78 * 128 + 64 * 64) * 4;  // 96256
    const int smem2 = (64 * 128 + 60 * 128 + 64 * 64) * 4;  // 79872
    cudaFuncSetAttribute(edge_gemm<78, 37, XUP, 10>,
                         cudaFuncAttributeMaxDynamicSharedMemorySize, smem1);
    cudaFuncSetAttribute(edge_gemm<60, 28, 28, 7>,
                         cudaFuncAttributeMaxDynamicSharedMemorySize, smem2);

    int nb = (NN + 255) / 256;
    int eb = NE / 128;  // 6250, exact

    k1_node<<<nb, 256>>>(x, u, hnh, hnc, Wih_n, Whh_n, bih_n, bhh_n, out_nh, out_nc);
    edge_gemm<78, 37, XUP, 10><<<eb, 128, smem1>>>(
        ei, ea, We1, be1, We2, be2, (const float*)p_xu, (float*)p_msum, 1);
    k3_edge_lstm<<<nb, 256>>>(heh, hec, Wih_e, Whh_e, bih_e, bhh_e, out_eh, out_ec);
    edge_gemm<60, 28, 28, 7><<<eb, 128, smem2>>>(
        ei, ea, Wo1, bo1, Wo2, bo2, (const float*)p_full, (float*)p_esum, 0);
    k5_out<<<nb, 256>>>(Wn1, bn1, Wn2, bn2, out_y);
}